// round 1
// baseline (speedup 1.0000x reference)
#include <cuda_runtime.h>
#include <cuda_bf16.h>
#include <math.h>

#define NS 32   // NSAMPLE
#define WARPS_PER_BLOCK 8

// One warp per query point.
// Phase 1: ball query (first NS in-ball indices in ascending order, early exit).
// Phase 2: epilogue — grouped_xyz (centered), weights, idx, grouped features,
//          written channel-major so each warp-wide store is 128B coalesced.
__global__ void __launch_bounds__(WARPS_PER_BLOCK * 32)
qgd_kernel(const float* __restrict__ xyz,
           const int*   __restrict__ xyz_cnt,
           const float* __restrict__ new_xyz,
           const float* __restrict__ new_r,
           const int*   __restrict__ new_cnt,
           const float* __restrict__ feat,
           const float* __restrict__ td,
           float* __restrict__ out_nf,    // (M_tot, 3+C, NS)
           float* __restrict__ out_w,     // (M_tot, NS)
           float* __restrict__ out_idx,   // (M_tot, NS)  idx cast to float
           int B, int M_tot, int C)
{
    __shared__ int sh_idx[WARPS_PER_BLOCK][NS];

    const int wib  = threadIdx.x >> 5;
    const int lane = threadIdx.x & 31;
    const int m = blockIdx.x * WARPS_PER_BLOCK + wib;
    if (m >= M_tot) return;   // warp-uniform

    // ---- find batch of query m (B is tiny) ----
    int moff = 0, noff = 0, nb = 0;
    for (int i = 0; i < B; i++) {
        int mc = new_cnt[i];
        int nc = xyz_cnt[i];
        if (m < moff + mc) { nb = nc; break; }
        moff += mc;
        noff += nc;
    }

    const float cx = new_xyz[m * 3 + 0];
    const float cy = new_xyz[m * 3 + 1];
    const float cz = new_xyz[m * 3 + 2];
    const float rt = 0.1f * td[0];             // TEMPERATURE * decay
    const float r0 = new_r[m];
    const float re = r0 + rt * 5.0f;           // explore radius
    const float r2 = re * re;

    const float* __restrict__ xb = xyz + (size_t)noff * 3;

    // ---- ball query: first NS hits in index order ----
    int cnt = 0;
    for (int start = 0; start < nb; start += 32) {
        const int pi = start + lane;
        bool hit = false;
        if (pi < nb) {
            const float dx = xb[pi * 3 + 0] - cx;
            const float dy = xb[pi * 3 + 1] - cy;
            const float dz = xb[pi * 3 + 2] - cz;
            hit = (dx * dx + dy * dy + dz * dz) < r2;
        }
        const unsigned mask = __ballot_sync(0xffffffffu, hit);
        if (hit) {
            const int slot = cnt + __popc(mask & ((1u << lane) - 1u));
            if (slot < NS) sh_idx[wib][slot] = pi;
        }
        cnt += __popc(mask);
        if (cnt >= NS) break;  // warp-uniform
    }
    __syncwarp();

    const bool empty  = (cnt == 0);
    const int  cclamp = cnt < NS ? cnt : NS;

    int my;  // batch-local point index for sample `lane`
    if (lane < cclamp)      my = sh_idx[wib][lane];
    else if (!empty)        my = sh_idx[wib][0];
    else                    my = 0;

    // ---- grouped xyz + dist + weight ----
    float dx = 0.0f, dy = 0.0f, dz = 0.0f;
    if (!empty) {
        dx = xb[my * 3 + 0] - cx;
        dy = xb[my * 3 + 1] - cy;
        dz = xb[my * 3 + 2] - cz;
    }
    const float dist = sqrtf(dx * dx + dy * dy + dz * dz);
    const float z = (dist - r0) / rt;
    // weights = 1 - sigmoid(z) = 1 / (1 + exp(z))
    const float w = 1.0f / (1.0f + __expf(z));

    const size_t nf_base = (size_t)m * (3 + C) * NS;
    out_nf[nf_base + 0 * NS + lane] = dx;
    out_nf[nf_base + 1 * NS + lane] = dy;
    out_nf[nf_base + 2 * NS + lane] = dz;
    out_w  [(size_t)m * NS + lane] = w;
    out_idx[(size_t)m * NS + lane] = (float)my;

    // ---- grouped features: lane = sample, loop channels ----
    float* __restrict__ nfo = out_nf + nf_base + 3 * NS + lane;
    if (empty) {
        for (int c = 0; c < C; c++) nfo[(size_t)c * NS] = 0.0f;
    } else if ((C & 3) == 0) {
        const float4* __restrict__ frow =
            (const float4*)(feat + ((size_t)(noff + my)) * C);
        const int c4n = C >> 2;
        #pragma unroll 8
        for (int c4 = 0; c4 < c4n; c4++) {
            const float4 v = frow[c4];
            nfo[(size_t)(c4 * 4 + 0) * NS] = v.x;
            nfo[(size_t)(c4 * 4 + 1) * NS] = v.y;
            nfo[(size_t)(c4 * 4 + 2) * NS] = v.z;
            nfo[(size_t)(c4 * 4 + 3) * NS] = v.w;
        }
    } else {
        const float* __restrict__ frow = feat + ((size_t)(noff + my)) * C;
        for (int c = 0; c < C; c++) nfo[(size_t)c * NS] = frow[c];
    }
}

extern "C" void kernel_launch(void* const* d_in, const int* in_sizes, int n_in,
                              void* d_out, int out_size)
{
    const float* xyz     = (const float*)d_in[0];
    const int*   xyz_cnt = (const int*)  d_in[1];
    const float* new_xyz = (const float*)d_in[2];
    const float* new_r   = (const float*)d_in[3];
    const int*   new_cnt = (const int*)  d_in[4];
    const float* feat    = (const float*)d_in[5];
    const float* td      = (const float*)d_in[6];

    const int B     = in_sizes[1];
    const int N_tot = in_sizes[0] / 3;
    const int M_tot = in_sizes[2] / 3;
    const int C     = in_sizes[5] / N_tot;

    float* out     = (float*)d_out;
    float* out_nf  = out;                                    // M_tot*(3+C)*NS
    float* out_w   = out_nf + (size_t)M_tot * (3 + C) * NS;  // M_tot*NS
    float* out_idx = out_w  + (size_t)M_tot * NS;            // M_tot*NS

    const int blocks = (M_tot + WARPS_PER_BLOCK - 1) / WARPS_PER_BLOCK;
    qgd_kernel<<<blocks, WARPS_PER_BLOCK * 32>>>(
        xyz, xyz_cnt, new_xyz, new_r, new_cnt, feat, td,
        out_nf, out_w, out_idx, B, M_tot, C);
}

// round 2
// speedup vs baseline: 2.6188x; 2.6188x over previous
#include <cuda_runtime.h>
#include <cuda_bf16.h>
#include <math.h>

#define NS 32            // NSAMPLE
#define WPB 4            // warps per block
#define MAXN (1 << 17)   // max total points (need 32768)

__device__ float g_x[MAXN];
__device__ float g_y[MAXN];
__device__ float g_z[MAXN];

__global__ void transpose_kernel(const float* __restrict__ xyz, int n)
{
    int i = blockIdx.x * blockDim.x + threadIdx.x;
    if (i < n) {
        g_x[i] = xyz[3 * i + 0];
        g_y[i] = xyz[3 * i + 1];
        g_z[i] = xyz[3 * i + 2];
    }
}

// One warp per query point. Ball query scans 128 points/iteration via SoA
// coalesced loads with register double-buffering; 4 ordered sub-ballots keep
// first-NS-in-index-order semantics. Epilogue writes are channel-major,
// 128B-coalesced per warp store.
__global__ void __launch_bounds__(WPB * 32)
qgd_kernel(const int*   __restrict__ xyz_cnt,
           const float* __restrict__ new_xyz,
           const float* __restrict__ new_r,
           const int*   __restrict__ new_cnt,
           const float* __restrict__ feat,
           const float* __restrict__ td,
           float* __restrict__ out_nf,    // (M_tot, 3+C, NS)
           float* __restrict__ out_w,     // (M_tot, NS)
           float* __restrict__ out_idx,   // (M_tot, NS)
           int B, int M_tot, int C)
{
    __shared__ int sh_idx[WPB][NS];

    const int wib  = threadIdx.x >> 5;
    const int lane = threadIdx.x & 31;
    const int m = blockIdx.x * WPB + wib;
    if (m >= M_tot) return;   // warp-uniform

    // ---- batch lookup (B tiny) ----
    int moff = 0, noff = 0, nb = 0;
    for (int i = 0; i < B; i++) {
        int mc = new_cnt[i];
        int nc = xyz_cnt[i];
        if (m < moff + mc) { nb = nc; break; }
        moff += mc;
        noff += nc;
    }

    const float cx = new_xyz[m * 3 + 0];
    const float cy = new_xyz[m * 3 + 1];
    const float cz = new_xyz[m * 3 + 2];
    const float rt = 0.1f * td[0];
    const float r0 = new_r[m];
    const float re = r0 + rt * 5.0f;
    const float r2 = re * re;

    const float* __restrict__ gx = g_x + noff;
    const float* __restrict__ gy = g_y + noff;
    const float* __restrict__ gz = g_z + noff;

    // ---- ball query: 128 points / iteration, double-buffered ----
    int cnt = 0;
    float xa[4], ya[4], za[4];
    {
        #pragma unroll
        for (int j = 0; j < 4; j++) {
            int pi = j * 32 + lane;
            int ps = pi < nb ? pi : nb - 1;
            xa[j] = gx[ps]; ya[j] = gy[ps]; za[j] = gz[ps];
        }
    }

    for (int start = 0; start < nb && cnt < NS; start += 128) {
        // prefetch next tile while current ballots resolve
        float xbuf[4], ybuf[4], zbuf[4];
        const int nstart = start + 128;
        if (nstart < nb) {
            #pragma unroll
            for (int j = 0; j < 4; j++) {
                int pi = nstart + j * 32 + lane;
                int ps = pi < nb ? pi : nb - 1;
                xbuf[j] = gx[ps]; ybuf[j] = gy[ps]; zbuf[j] = gz[ps];
            }
        }

        #pragma unroll
        for (int j = 0; j < 4; j++) {
            const int pi = start + j * 32 + lane;
            const float dx = xa[j] - cx;
            const float dy = ya[j] - cy;
            const float dz = za[j] - cz;
            const bool hit = (pi < nb) &&
                             (dx * dx + dy * dy + dz * dz < r2);
            const unsigned mask = __ballot_sync(0xffffffffu, hit);
            if (hit) {
                const int slot = cnt + __popc(mask & ((1u << lane) - 1u));
                if (slot < NS) sh_idx[wib][slot] = pi;
            }
            cnt += __popc(mask);
        }

        #pragma unroll
        for (int j = 0; j < 4; j++) { xa[j] = xbuf[j]; ya[j] = ybuf[j]; za[j] = zbuf[j]; }
    }
    __syncwarp();

    const bool empty  = (cnt == 0);
    const int  cclamp = cnt < NS ? cnt : NS;

    int my;
    if (lane < cclamp)      my = sh_idx[wib][lane];
    else if (!empty)        my = sh_idx[wib][0];
    else                    my = 0;

    // ---- grouped xyz + dist + weight ----
    float dx = 0.0f, dy = 0.0f, dz = 0.0f;
    if (!empty) {
        dx = gx[my] - cx;
        dy = gy[my] - cy;
        dz = gz[my] - cz;
    }
    const float dist = sqrtf(dx * dx + dy * dy + dz * dz);
    const float z = (dist - r0) / rt;
    const float w = 1.0f / (1.0f + __expf(z));   // 1 - sigmoid(z)

    const size_t nf_base = (size_t)m * (3 + C) * NS;
    out_nf[nf_base + 0 * NS + lane] = dx;
    out_nf[nf_base + 1 * NS + lane] = dy;
    out_nf[nf_base + 2 * NS + lane] = dz;
    out_w  [(size_t)m * NS + lane] = w;
    out_idx[(size_t)m * NS + lane] = (float)my;

    // ---- grouped features ----
    float* __restrict__ nfo = out_nf + nf_base + 3 * NS + lane;
    if (empty) {
        for (int c = 0; c < C; c++) nfo[(size_t)c * NS] = 0.0f;
    } else if ((C & 3) == 0) {
        const float4* __restrict__ frow =
            (const float4*)(feat + ((size_t)(noff + my)) * C);
        const int c4n = C >> 2;
        #pragma unroll 8
        for (int c4 = 0; c4 < c4n; c4++) {
            const float4 v = frow[c4];
            nfo[(size_t)(c4 * 4 + 0) * NS] = v.x;
            nfo[(size_t)(c4 * 4 + 1) * NS] = v.y;
            nfo[(size_t)(c4 * 4 + 2) * NS] = v.z;
            nfo[(size_t)(c4 * 4 + 3) * NS] = v.w;
        }
    } else {
        const float* __restrict__ frow = feat + ((size_t)(noff + my)) * C;
        for (int c = 0; c < C; c++) nfo[(size_t)c * NS] = frow[c];
    }
}

extern "C" void kernel_launch(void* const* d_in, const int* in_sizes, int n_in,
                              void* d_out, int out_size)
{
    const float* xyz     = (const float*)d_in[0];
    const int*   xyz_cnt = (const int*)  d_in[1];
    const float* new_xyz = (const float*)d_in[2];
    const float* new_r   = (const float*)d_in[3];
    const int*   new_cnt = (const int*)  d_in[4];
    const float* feat    = (const float*)d_in[5];
    const float* td      = (const float*)d_in[6];

    const int B     = in_sizes[1];
    const int N_tot = in_sizes[0] / 3;
    const int M_tot = in_sizes[2] / 3;
    const int C     = in_sizes[5] / N_tot;

    float* out     = (float*)d_out;
    float* out_nf  = out;
    float* out_w   = out_nf + (size_t)M_tot * (3 + C) * NS;
    float* out_idx = out_w  + (size_t)M_tot * NS;

    transpose_kernel<<<(N_tot + 255) / 256, 256>>>(xyz, N_tot);

    const int blocks = (M_tot + WPB - 1) / WPB;
    qgd_kernel<<<blocks, WPB * 32>>>(
        xyz_cnt, new_xyz, new_r, new_cnt, feat, td,
        out_nf, out_w, out_idx, B, M_tot, C);
}

// round 3
// speedup vs baseline: 3.5132x; 1.3415x over previous
#include <cuda_runtime.h>
#include <cuda_bf16.h>
#include <math.h>

#define NS 32            // NSAMPLE
#define WPB 4            // warps per block (phase A)
#define MAXN (1 << 17)   // max total points
#define MAXM (1 << 14)   // max total queries
#define TLIM 2048        // phase-A scan limit (points)
#define TBW 8            // phase-B warps per block

__device__ float g_x[MAXN];
__device__ float g_y[MAXN];
__device__ float g_z[MAXN];
__device__ int   g_list[MAXM];
__device__ int   g_count;

__global__ void transpose_kernel(const float* __restrict__ xyz, int n)
{
    int i = blockIdx.x * blockDim.x + threadIdx.x;
    if (i == 0) g_count = 0;
    if (i < n) {
        g_x[i] = xyz[3 * i + 0];
        g_y[i] = xyz[3 * i + 1];
        g_z[i] = xyz[3 * i + 2];
    }
}

// ---------------- Phase A: warp per query, bounded scan ----------------
__global__ void __launch_bounds__(WPB * 32)
qgd_kernel(const int*   __restrict__ xyz_cnt,
           const float* __restrict__ new_xyz,
           const float* __restrict__ new_r,
           const int*   __restrict__ new_cnt,
           const float* __restrict__ feat,
           const float* __restrict__ td,
           float* __restrict__ out_nf,
           float* __restrict__ out_w,
           float* __restrict__ out_idx,
           int B, int M_tot, int C)
{
    __shared__ int sh_idx[WPB][NS];

    const int wib  = threadIdx.x >> 5;
    const int lane = threadIdx.x & 31;
    const int m = blockIdx.x * WPB + wib;
    if (m >= M_tot) return;

    int moff = 0, noff = 0, nb = 0;
    for (int i = 0; i < B; i++) {
        int mc = new_cnt[i];
        int nc = xyz_cnt[i];
        if (m < moff + mc) { nb = nc; break; }
        moff += mc;
        noff += nc;
    }

    const float cx = new_xyz[m * 3 + 0];
    const float cy = new_xyz[m * 3 + 1];
    const float cz = new_xyz[m * 3 + 2];
    const float rt = 0.1f * td[0];
    const float r0 = new_r[m];
    const float re = r0 + rt * 5.0f;
    const float r2 = re * re;

    const float* __restrict__ gx = g_x + noff;
    const float* __restrict__ gy = g_y + noff;
    const float* __restrict__ gz = g_z + noff;

    const int L = nb < TLIM ? nb : TLIM;

    int cnt = 0;
    float xa[4], ya[4], za[4];
    #pragma unroll
    for (int j = 0; j < 4; j++) {
        int pi = j * 32 + lane;
        int ps = pi < nb ? pi : nb - 1;
        xa[j] = gx[ps]; ya[j] = gy[ps]; za[j] = gz[ps];
    }

    for (int start = 0; start < L && cnt < NS; start += 128) {
        float xbuf[4], ybuf[4], zbuf[4];
        const int nstart = start + 128;
        if (nstart < L) {
            #pragma unroll
            for (int j = 0; j < 4; j++) {
                int pi = nstart + j * 32 + lane;
                int ps = pi < nb ? pi : nb - 1;
                xbuf[j] = gx[ps]; ybuf[j] = gy[ps]; zbuf[j] = gz[ps];
            }
        }
        #pragma unroll
        for (int j = 0; j < 4; j++) {
            const int pi = start + j * 32 + lane;
            const float dx = xa[j] - cx;
            const float dy = ya[j] - cy;
            const float dz = za[j] - cz;
            const bool hit = (pi < L) && (dx * dx + dy * dy + dz * dz < r2);
            const unsigned mask = __ballot_sync(0xffffffffu, hit);
            if (hit) {
                const int slot = cnt + __popc(mask & ((1u << lane) - 1u));
                if (slot < NS) sh_idx[wib][slot] = pi;
            }
            cnt += __popc(mask);
        }
        #pragma unroll
        for (int j = 0; j < 4; j++) { xa[j] = xbuf[j]; ya[j] = ybuf[j]; za[j] = zbuf[j]; }
    }
    __syncwarp();

    // unsatisfied and more points remain -> defer to phase B
    if (cnt < NS && nb > TLIM) {
        if (lane == 0) {
            int pos = atomicAdd(&g_count, 1);
            g_list[pos] = m;
        }
        return;
    }

    const bool empty  = (cnt == 0);
    const int  cclamp = cnt < NS ? cnt : NS;

    int my;
    if (lane < cclamp)      my = sh_idx[wib][lane];
    else if (!empty)        my = sh_idx[wib][0];
    else                    my = 0;

    float dx = 0.0f, dy = 0.0f, dz = 0.0f;
    if (!empty) {
        dx = gx[my] - cx;
        dy = gy[my] - cy;
        dz = gz[my] - cz;
    }
    const float dist = sqrtf(dx * dx + dy * dy + dz * dz);
    const float z = (dist - r0) / rt;
    const float w = 1.0f / (1.0f + __expf(z));

    const size_t nf_base = (size_t)m * (3 + C) * NS;
    out_nf[nf_base + 0 * NS + lane] = dx;
    out_nf[nf_base + 1 * NS + lane] = dy;
    out_nf[nf_base + 2 * NS + lane] = dz;
    out_w  [(size_t)m * NS + lane] = w;
    out_idx[(size_t)m * NS + lane] = (float)my;

    float* __restrict__ nfo = out_nf + nf_base + 3 * NS + lane;
    if (empty) {
        for (int c = 0; c < C; c++) nfo[(size_t)c * NS] = 0.0f;
    } else if ((C & 3) == 0) {
        const float4* __restrict__ frow =
            (const float4*)(feat + ((size_t)(noff + my)) * C);
        const int c4n = C >> 2;
        #pragma unroll 8
        for (int c4 = 0; c4 < c4n; c4++) {
            const float4 v = frow[c4];
            nfo[(size_t)(c4 * 4 + 0) * NS] = v.x;
            nfo[(size_t)(c4 * 4 + 1) * NS] = v.y;
            nfo[(size_t)(c4 * 4 + 2) * NS] = v.z;
            nfo[(size_t)(c4 * 4 + 3) * NS] = v.w;
        }
    } else {
        const float* __restrict__ frow = feat + ((size_t)(noff + my)) * C;
        for (int c = 0; c < C; c++) nfo[(size_t)c * NS] = frow[c];
    }
}

// ---------------- Phase B: block per hard query ----------------
__global__ void __launch_bounds__(TBW * 32)
qgd_tail_kernel(const int*   __restrict__ xyz_cnt,
                const float* __restrict__ new_xyz,
                const float* __restrict__ new_r,
                const int*   __restrict__ new_cnt,
                const float* __restrict__ feat,
                const float* __restrict__ td,
                float* __restrict__ out_nf,
                float* __restrict__ out_w,
                float* __restrict__ out_idx,
                int B, int M_tot, int C)
{
    __shared__ int s_idx[NS];
    __shared__ int s_wcnt[TBW];

    const int tid  = threadIdx.x;
    const int wib  = tid >> 5;
    const int lane = tid & 31;
    const int nwork = g_count;

    for (int wl = blockIdx.x; wl < nwork; wl += gridDim.x) {
        const int m = g_list[wl];

        int moff = 0, noff = 0, nb = 0;
        for (int i = 0; i < B; i++) {
            int mc = new_cnt[i];
            int nc = xyz_cnt[i];
            if (m < moff + mc) { nb = nc; break; }
            moff += mc;
            noff += nc;
        }

        const float cx = new_xyz[m * 3 + 0];
        const float cy = new_xyz[m * 3 + 1];
        const float cz = new_xyz[m * 3 + 2];
        const float rt = 0.1f * td[0];
        const float r0 = new_r[m];
        const float re = r0 + rt * 5.0f;
        const float r2 = re * re;

        const float* __restrict__ gx = g_x + noff;
        const float* __restrict__ gy = g_y + noff;
        const float* __restrict__ gz = g_z + noff;

        int cnt = 0;
        // 1024 points per iteration: warp w covers [start + w*128, +128)
        for (int start = 0; start < nb && cnt < NS; start += TBW * 128) {
            unsigned masks[4];
            int wtot = 0;
            #pragma unroll
            for (int j = 0; j < 4; j++) {
                const int pi = start + wib * 128 + j * 32 + lane;
                bool hit = false;
                if (pi < nb) {
                    const float dx = gx[pi] - cx;
                    const float dy = gy[pi] - cy;
                    const float dz = gz[pi] - cz;
                    hit = dx * dx + dy * dy + dz * dz < r2;
                }
                masks[j] = __ballot_sync(0xffffffffu, hit);
                wtot += __popc(masks[j]);
            }
            if (lane == 0) s_wcnt[wib] = wtot;
            __syncthreads();

            int base = cnt, total = cnt;
            #pragma unroll
            for (int i = 0; i < TBW; i++) {
                int c = s_wcnt[i];
                if (i < wib) base += c;
                total += c;
            }
            int off = base;
            #pragma unroll
            for (int j = 0; j < 4; j++) {
                const bool hit = (masks[j] >> lane) & 1u;
                if (hit) {
                    const int slot = off + __popc(masks[j] & ((1u << lane) - 1u));
                    if (slot < NS)
                        s_idx[slot] = start + wib * 128 + j * 32 + lane;
                }
                off += __popc(masks[j]);
            }
            cnt = total;
            __syncthreads();
        }

        const bool empty  = (cnt == 0);
        const int  cclamp = cnt < NS ? cnt : NS;

        int my;
        if (lane < cclamp)      my = s_idx[lane];
        else if (!empty)        my = s_idx[0];
        else                    my = 0;

        const size_t nf_base = (size_t)m * (3 + C) * NS;

        if (wib == 0) {
            float dx = 0.0f, dy = 0.0f, dz = 0.0f;
            if (!empty) {
                dx = gx[my] - cx;
                dy = gy[my] - cy;
                dz = gz[my] - cz;
            }
            const float dist = sqrtf(dx * dx + dy * dy + dz * dz);
            const float z = (dist - r0) / rt;
            const float w = 1.0f / (1.0f + __expf(z));
            out_nf[nf_base + 0 * NS + lane] = dx;
            out_nf[nf_base + 1 * NS + lane] = dy;
            out_nf[nf_base + 2 * NS + lane] = dz;
            out_w  [(size_t)m * NS + lane] = w;
            out_idx[(size_t)m * NS + lane] = (float)my;
        }

        // features: warp wib handles channels c = wib, wib+TBW, ...
        const float* __restrict__ frow = feat + ((size_t)(noff + my)) * C;
        for (int c = wib; c < C; c += TBW) {
            const float v = empty ? 0.0f : frow[c];
            out_nf[nf_base + (size_t)(3 + c) * NS + lane] = v;
        }
        __syncthreads();
    }
}

extern "C" void kernel_launch(void* const* d_in, const int* in_sizes, int n_in,
                              void* d_out, int out_size)
{
    const float* xyz     = (const float*)d_in[0];
    const int*   xyz_cnt = (const int*)  d_in[1];
    const float* new_xyz = (const float*)d_in[2];
    const float* new_r   = (const float*)d_in[3];
    const int*   new_cnt = (const int*)  d_in[4];
    const float* feat    = (const float*)d_in[5];
    const float* td      = (const float*)d_in[6];

    const int B     = in_sizes[1];
    const int N_tot = in_sizes[0] / 3;
    const int M_tot = in_sizes[2] / 3;
    const int C     = in_sizes[5] / N_tot;

    float* out     = (float*)d_out;
    float* out_nf  = out;
    float* out_w   = out_nf + (size_t)M_tot * (3 + C) * NS;
    float* out_idx = out_w  + (size_t)M_tot * NS;

    transpose_kernel<<<(N_tot + 255) / 256, 256>>>(xyz, N_tot);

    const int blocksA = (M_tot + WPB - 1) / WPB;
    qgd_kernel<<<blocksA, WPB * 32>>>(
        xyz_cnt, new_xyz, new_r, new_cnt, feat, td,
        out_nf, out_w, out_idx, B, M_tot, C);

    qgd_tail_kernel<<<1024, TBW * 32>>>(
        xyz_cnt, new_xyz, new_r, new_cnt, feat, td,
        out_nf, out_w, out_idx, B, M_tot, C);
}